// round 11
// baseline (speedup 1.0000x reference)
#include <cuda_runtime.h>
#include <cuda_fp16.h>
#include <cuda_bf16.h>
#include <cstdint>

#define N_NODES 100000
#define N_EDGES 3200000
#define IN_CH   128
#define HID     32
#define OUT_CH  64
#define N_SG    31
#define N_RAW   (N_EDGES + N_NODES)          // edges + self loops (unpadded)
#define N_PAD_MAX (N_EDGES + 8 * N_NODES)    // padded CSR capacity (4.0M, mult of 8)

// ---------------- device scratch (static globals; no allocation) ----------------
__device__ int    g_is64;
__device__ int    g_deg[N_NODES];
__device__ float  g_dinv[N_NODES];
__device__ int    g_offs[N_NODES + 1];
__device__ int    g_cursor[N_NODES];
__device__ int    g_normi[N_SG + 2];         // per-stage max |stored| (float bits, >=0)
__device__ int4   g_csr4[N_PAD_MAX / 4];     // src indices, padded w/ sentinel N_NODES
// fp16 ping-pong scaled state (row N_NODES = zeros). Row = 32 half = 64B.
__device__ __half g_h16[2][(size_t)(N_NODES + 1) * HID];

__device__ __forceinline__ float stage_max(int s) {
    return fmaxf(__int_as_float(g_normi[s]), 1e-30f);
}

// warp-reduce max (val >= 0) and atomic into g_normi[s]
__device__ __forceinline__ void record_max(float v, int s, int lane) {
#pragma unroll
    for (int d = 16; d >= 1; d >>= 1)
        v = fmaxf(v, __shfl_xor_sync(0xffffffffu, v, d));
    if (lane == 0) atomicMax(&g_normi[s], __float_as_int(v));
}

// Safe edge accessor: idx in [0, 2*N_EDGES)
__device__ __forceinline__ int edge_at(const void* ei, size_t idx) {
    int v = g_is64 ? (int)((const long long*)ei)[idx]
                   : ((const int*)ei)[idx];
    return min(max(v, 0), N_NODES - 1);
}

// ---------------- launch 1: dtype detect + deg init ----------------
__global__ void k_detect_init(const int* __restrict__ w) {
    int i = blockIdx.x * blockDim.x + threadIdx.x;
    if (i < N_NODES) g_deg[i] = 1;  // self loop
    if (blockIdx.x == 0) {
        __shared__ int any_nonzero;
        if (threadIdx.x == 0) any_nonzero = 0;
        __syncthreads();
        size_t pos = (size_t)threadIdx.x * 24994 + 1;   // tid<256 -> max 6.37M
        if (w[pos] != 0) any_nonzero = 1;
        __syncthreads();
        if (threadIdx.x == 0) g_is64 = any_nonzero ? 0 : 1;
    }
}

// ---------------- launch 2: degree accumulation ----------------
__global__ void k_deg_accum(const void* __restrict__ ei) {
    int i = blockIdx.x * blockDim.x + threadIdx.x;
    if (i < N_EDGES) {
        int c = edge_at(ei, (size_t)N_EDGES + i);   // col = edge_index[1] (dst)
        atomicAdd(&g_deg[c], 1);
    }
}

// ---------------- launch 3: dinv + padded exclusive scan + cursor init ----------------
__global__ void k_scan_dinv() {
    __shared__ int part[1024];
    const int tid = threadIdx.x;
    const int chunk = (N_NODES + 1023) / 1024;
    int beg = tid * chunk;
    int end = min(beg + chunk, N_NODES);
    int s = 0;
    for (int i = beg; i < end; i++) {
        int d = g_deg[i];
        g_dinv[i] = rsqrtf((float)d);
        s += (d + 7) & ~7;                      // pad each segment to mult of 8
    }
    part[tid] = s;
    __syncthreads();
    for (int off = 1; off < 1024; off <<= 1) {
        int v = (tid >= off) ? part[tid - off] : 0;
        __syncthreads();
        part[tid] += v;
        __syncthreads();
    }
    int run = (tid == 0) ? 0 : part[tid - 1];
    for (int i = beg; i < end; i++) {
        g_offs[i] = run;
        g_cursor[i] = run;
        run += (g_deg[i] + 7) & ~7;
    }
    if (tid == 1023) g_offs[N_NODES] = run;
}

// ---------------- launch 4: CSR sentinel fill + zero sentinel h rows + norm reset ----------------
__global__ void k_prep() {
    int i = blockIdx.x * blockDim.x + threadIdx.x;
    if (i < N_PAD_MAX / 4) g_csr4[i] = make_int4(N_NODES, N_NODES, N_NODES, N_NODES);
    if (i < 2 * HID) {  // zero row N_NODES of both ping-pong buffers
        g_h16[i >> 5][(size_t)N_NODES * HID + (i & 31)] = __float2half(0.f);
    }
    if (i < N_SG + 2) g_normi[i] = 0;
}

// ---------------- launch 5: CSR fill (+ self loops)  AND  conv0 (fused) ----------------
#define FILL_B ((N_RAW + 255) / 256)         // 12891
#define CONV_B ((N_NODES + 7) / 8)           // 12500
__global__ void __launch_bounds__(256) k_fill_conv0(const void* __restrict__ ei,
                                                    const float* __restrict__ x,
                                                    const float* __restrict__ W0,
                                                    const float* __restrict__ b0) {
    __shared__ float Wsm[IN_CH * HID];   // 16 KB (used by conv0 blocks only)
    __shared__ float bsm[HID];
    if (blockIdx.x < FILL_B) {
        int i = blockIdx.x * blockDim.x + threadIdx.x;
        int* csr = (int*)g_csr4;
        if (i < N_EDGES) {
            int r = edge_at(ei, (size_t)i);               // src
            int c = edge_at(ei, (size_t)N_EDGES + i);     // dst
            int pos = atomicAdd(&g_cursor[c], 1);
            csr[min(max(pos, 0), N_PAD_MAX - 1)] = r;
        } else if (i < N_RAW) {
            int n = i - N_EDGES;
            int pos = atomicAdd(&g_cursor[n], 1);
            csr[min(max(pos, 0), N_PAD_MAX - 1)] = n;     // self loop
        }
        return;
    }
    // ---- conv0: raw_0 = dinv * (x @ W0 + b0), stored fp16; max -> g_normi[0] ----
    for (int i = threadIdx.x; i < IN_CH * HID; i += blockDim.x) Wsm[i] = W0[i];
    if (threadIdx.x < HID) bsm[threadIdx.x] = b0[threadIdx.x];
    __syncthreads();
    int node = (blockIdx.x - FILL_B) * 8 + (threadIdx.x >> 5);
    int lane = threadIdx.x & 31;
    if (node >= N_NODES) return;
    float xr[4];
#pragma unroll
    for (int q = 0; q < 4; q++) xr[q] = x[(size_t)node * IN_CH + q * 32 + lane];
    float y = bsm[lane];
#pragma unroll
    for (int q = 0; q < 4; q++)
#pragma unroll
        for (int c = 0; c < 32; c++) {
            float xv = __shfl_sync(0xffffffffu, xr[q], c);
            y = fmaf(xv, Wsm[(q * 32 + c) * HID + lane], y);
        }
    float sv = y * g_dinv[node];
    g_h16[0][(size_t)node * HID + lane] = __float2half(sv);
    record_max(fabsf(sv), 0, lane);
}

// ---------------- launches 6..36: SG layer (fp16 state, fp32 math, renormalized) ----------------
// Stored input raw_l satisfies raw_l = c_{l-1} * h'_l with c known via g_norm.
// Layer l: inv = 1/M_l; out = relu( (agg@W)*dv*inv + cb*b ) * dv;  max(out) -> g_normi[l+1]
// Lane layout: 8 groups (grp=lane>>2) x 4 subs (sub=lane&3). Group g handles edge g
// of each 8-edge chunk; thread reads 16B = 8 fp16 channels [sub*8 .. sub*8+7].
__device__ __forceinline__ int pick8(int4 s0, int4 s1, int grp) {
    int4 s = (grp & 4) ? s1 : s0;
    int m = grp & 3;
    return (m == 0) ? s.x : (m == 1) ? s.y : (m == 2) ? s.z : s.w;
}

__device__ __forceinline__ void acc_add(float2* A, uint4 v) {
    float2 f0 = __half22float2(*(__half2*)&v.x);
    float2 f1 = __half22float2(*(__half2*)&v.y);
    float2 f2 = __half22float2(*(__half2*)&v.z);
    float2 f3 = __half22float2(*(__half2*)&v.w);
    A[0].x += f0.x; A[0].y += f0.y;
    A[1].x += f1.x; A[1].y += f1.y;
    A[2].x += f2.x; A[2].y += f2.y;
    A[3].x += f3.x; A[3].y += f3.y;
}

__global__ void __launch_bounds__(256) k_sg_layer(int parity, int l,
                                                  const float* __restrict__ W,
                                                  const float* __restrict__ b) {
    __shared__ float Wsm[HID * HID];
    __shared__ float bsm[HID];
    for (int i = threadIdx.x; i < HID * HID; i += blockDim.x) Wsm[i] = W[i];
    if (threadIdx.x < HID) bsm[threadIdx.x] = b[threadIdx.x];
    __syncthreads();
    int node = blockIdx.x * 8 + (threadIdx.x >> 5);
    int lane = threadIdx.x & 31;
    if (node >= N_NODES) return;

    // normalization scalars (uniform; L1-cached broadcast loads)
    float inv = 1.f / stage_max(l);
    float cb = inv;                       // cumulative Π 1/M_j for bias scaling
    for (int j = 0; j < l; j++) cb /= stage_max(j);

    const uint4* __restrict__ hin = (const uint4*)g_h16[parity];  // row = 4 uint4
    __half* __restrict__ hout = g_h16[parity ^ 1];

    int e8   = g_offs[node] >> 3;     // segments padded to mult of 8
    int end8 = g_offs[node + 1] >> 3;
    const int grp = lane >> 2, sub = lane & 3;

    float2 A[4] = {{0.f,0.f},{0.f,0.f},{0.f,0.f},{0.f,0.f}};
    float2 B[4] = {{0.f,0.f},{0.f,0.f},{0.f,0.f},{0.f,0.f}};

    // 16 edges per iteration: 4 CSR quads, 2 independent gathers per thread
    for (; e8 + 2 <= end8; e8 += 2) {
        int4 s0 = __ldg(&g_csr4[2 * e8]);
        int4 s1 = __ldg(&g_csr4[2 * e8 + 1]);
        int4 s2 = __ldg(&g_csr4[2 * e8 + 2]);
        int4 s3 = __ldg(&g_csr4[2 * e8 + 3]);
        int srcA = pick8(s0, s1, grp);
        int srcB = pick8(s2, s3, grp);
        uint4 va = hin[srcA * 4 + sub];
        uint4 vb = hin[srcB * 4 + sub];
        acc_add(A, va);
        acc_add(B, vb);
    }
    if (e8 < end8) {
        int4 s0 = __ldg(&g_csr4[2 * e8]);
        int4 s1 = __ldg(&g_csr4[2 * e8 + 1]);
        int srcA = pick8(s0, s1, grp);
        uint4 va = hin[srcA * 4 + sub];
        acc_add(A, va);
    }
#pragma unroll
    for (int i = 0; i < 4; i++) { A[i].x += B[i].x; A[i].y += B[i].y; }

    // reduce across the 8 groups (strides 4,8,16 flip grp bits)
#pragma unroll
    for (int d = 4; d <= 16; d <<= 1) {
#pragma unroll
        for (int i = 0; i < 4; i++) {
            A[i].x += __shfl_xor_sync(0xffffffffu, A[i].x, d);
            A[i].y += __shfl_xor_sync(0xffffffffu, A[i].y, d);
        }
    }
    // channel c lives at lanes with sub==c>>3, component c&7; broadcast from lane c>>3.
    float y = 0.f;
#pragma unroll
    for (int c = 0; c < 32; c++) {
        float comp = ((c & 7) == 0) ? A[0].x : ((c & 7) == 1) ? A[0].y :
                     ((c & 7) == 2) ? A[1].x : ((c & 7) == 3) ? A[1].y :
                     ((c & 7) == 4) ? A[2].x : ((c & 7) == 5) ? A[2].y :
                     ((c & 7) == 6) ? A[3].x : A[3].y;
        float v = __shfl_sync(0xffffffffu, comp, c >> 3);
        y = fmaf(v, Wsm[c * HID + lane], y);
    }
    float dv = g_dinv[node];
    float t = fmaf(y, dv * inv, cb * bsm[lane]);
    float sv = fmaxf(t, 0.f) * dv;                 // pre-scale for next layer
    hout[node * HID + lane] = __float2half(sv);
    record_max(sv, l + 1, lane);
}

// ---------------- final launch: out = h @ W32 + b32 ----------------
// true h'_31 = raw_31 * Π_{j=0..30} M_j; unscale h' by sqrt(deg).
__global__ void k_conv_out(int parity, const float* __restrict__ W32,
                           const float* __restrict__ b32, float* __restrict__ out) {
    __shared__ float Wsm[HID * OUT_CH];  // 8 KB
    __shared__ float bsm[OUT_CH];
    for (int i = threadIdx.x; i < HID * OUT_CH; i += blockDim.x) Wsm[i] = W32[i];
    if (threadIdx.x < OUT_CH) bsm[threadIdx.x] = b32[threadIdx.x];
    __syncthreads();
    int node = blockIdx.x * 8 + (threadIdx.x >> 5);
    int lane = threadIdx.x & 31;
    if (node >= N_NODES) return;
    float prod = 1.f;
    for (int j = 0; j <= N_SG - 1; j++) prod *= stage_max(j);   // M_0..M_30
    float hv = __half2float(g_h16[parity][(size_t)node * HID + lane])
               * prod * sqrtf((float)g_deg[node]);
    float y0 = bsm[lane], y1 = bsm[lane + 32];
#pragma unroll
    for (int c = 0; c < 32; c++) {
        float a = __shfl_sync(0xffffffffu, hv, c);
        y0 = fmaf(a, Wsm[c * OUT_CH + lane], y0);
        y1 = fmaf(a, Wsm[c * OUT_CH + lane + 32], y1);
    }
    out[(size_t)node * OUT_CH + lane]      = y0;
    out[(size_t)node * OUT_CH + lane + 32] = y1;
}

// ---------------- launch ----------------
extern "C" void kernel_launch(void* const* d_in, const int* in_sizes, int n_in,
                              void* d_out, int out_size) {
    const float* x = nullptr; const float* W0 = nullptr; const float* b0 = nullptr;
    const float* Ws = nullptr; const float* bs = nullptr;
    const float* W32 = nullptr; const float* b32 = nullptr;
    const void* ei = nullptr;
    for (int i = 0; i < n_in; i++) {
        switch (in_sizes[i]) {
            case 12800000: x   = (const float*)d_in[i]; break;
            case 4096:     W0  = (const float*)d_in[i]; break;
            case 32:       b0  = (const float*)d_in[i]; break;
            case 31744:    Ws  = (const float*)d_in[i]; break;
            case 992:      bs  = (const float*)d_in[i]; break;
            case 2048:     W32 = (const float*)d_in[i]; break;
            case 64:       b32 = (const float*)d_in[i]; break;
            case 6400000:  ei  = d_in[i]; break;
            default: break;
        }
    }
    if (!x || !W0 || !b0 || !Ws || !bs || !W32 || !b32 || !ei) return;

    float* out = (float*)d_out;
    const int T = 256;

    k_detect_init<<<(N_NODES + T - 1) / T, T>>>((const int*)ei);          // 1
    k_deg_accum<<<(N_EDGES + T - 1) / T, T>>>(ei);                        // 2
    k_scan_dinv<<<1, 1024>>>();                                           // 3
    k_prep<<<(N_PAD_MAX / 4 + T - 1) / T, T>>>();                         // 4
    k_fill_conv0<<<FILL_B + CONV_B, T>>>(ei, x, W0, b0);                  // 5

    int parity = 0;
    for (int l = 0; l < N_SG; l++) {                                      // 6..36
        k_sg_layer<<<CONV_B, T>>>(parity, l, Ws + (size_t)l * HID * HID, bs + (size_t)l * HID);
        parity ^= 1;
    }

    k_conv_out<<<CONV_B, T>>>(parity, W32, b32, out);                     // 37
}

// round 12
// speedup vs baseline: 1.5859x; 1.5859x over previous
#include <cuda_runtime.h>
#include <cuda_fp16.h>
#include <cuda_bf16.h>
#include <cstdint>

#define N_NODES 100000
#define N_EDGES 3200000
#define IN_CH   128
#define HID     32
#define OUT_CH  64
#define N_SG    31
#define N_RAW   (N_EDGES + N_NODES)          // edges + self loops (unpadded)
#define N_PAD_MAX (N_EDGES + 8 * N_NODES)    // padded CSR capacity (4.0M, mult of 8)

// ---------------- device scratch (static globals; no allocation) ----------------
__device__ int    g_is64;
__device__ int    g_deg[N_NODES];
__device__ float  g_dinv[N_NODES];
__device__ int    g_offs[N_NODES + 1];
__device__ int    g_cursor[N_NODES];
__device__ int    g_normi[N_SG + 2];         // per-stage max |stored| (float bits, >=0)
__device__ int4   g_csr4[N_PAD_MAX / 4];     // src indices, padded w/ sentinel N_NODES
// fp16 ping-pong scaled state (row N_NODES = zeros). Row = 32 half = 64B.
__device__ __half g_h16[2][(size_t)(N_NODES + 1) * HID];

__device__ __forceinline__ float stage_max(int s) {
    return fmaxf(__int_as_float(g_normi[s]), 1e-30f);
}

// Safe edge accessor: idx in [0, 2*N_EDGES)
__device__ __forceinline__ int edge_at(const void* ei, size_t idx) {
    int v = g_is64 ? (int)((const long long*)ei)[idx]
                   : ((const int*)ei)[idx];
    return min(max(v, 0), N_NODES - 1);
}

// ---------------- launch 1: dtype detect + deg init ----------------
__global__ void k_detect_init(const int* __restrict__ w) {
    int i = blockIdx.x * blockDim.x + threadIdx.x;
    if (i < N_NODES) g_deg[i] = 1;  // self loop
    if (blockIdx.x == 0) {
        __shared__ int any_nonzero;
        if (threadIdx.x == 0) any_nonzero = 0;
        __syncthreads();
        size_t pos = (size_t)threadIdx.x * 24994 + 1;   // tid<256 -> max 6.37M
        if (w[pos] != 0) any_nonzero = 1;
        __syncthreads();
        if (threadIdx.x == 0) g_is64 = any_nonzero ? 0 : 1;
    }
}

// ---------------- launch 2: degree accumulation ----------------
__global__ void k_deg_accum(const void* __restrict__ ei) {
    int i = blockIdx.x * blockDim.x + threadIdx.x;
    if (i < N_EDGES) {
        int c = edge_at(ei, (size_t)N_EDGES + i);   // col = edge_index[1] (dst)
        atomicAdd(&g_deg[c], 1);
    }
}

// ---------------- launch 3: dinv + padded exclusive scan + cursor init ----------------
__global__ void k_scan_dinv() {
    __shared__ int part[1024];
    const int tid = threadIdx.x;
    const int chunk = (N_NODES + 1023) / 1024;
    int beg = tid * chunk;
    int end = min(beg + chunk, N_NODES);
    int s = 0;
    for (int i = beg; i < end; i++) {
        int d = g_deg[i];
        g_dinv[i] = rsqrtf((float)d);
        s += (d + 7) & ~7;                      // pad each segment to mult of 8
    }
    part[tid] = s;
    __syncthreads();
    for (int off = 1; off < 1024; off <<= 1) {
        int v = (tid >= off) ? part[tid - off] : 0;
        __syncthreads();
        part[tid] += v;
        __syncthreads();
    }
    int run = (tid == 0) ? 0 : part[tid - 1];
    for (int i = beg; i < end; i++) {
        g_offs[i] = run;
        g_cursor[i] = run;
        run += (g_deg[i] + 7) & ~7;
    }
    if (tid == 1023) g_offs[N_NODES] = run;
}

// ---------------- launch 4: CSR sentinel fill + zero sentinel h rows + norm reset ----------------
__global__ void k_prep() {
    int i = blockIdx.x * blockDim.x + threadIdx.x;
    if (i < N_PAD_MAX / 4) g_csr4[i] = make_int4(N_NODES, N_NODES, N_NODES, N_NODES);
    if (i < 2 * HID) {  // zero row N_NODES of both ping-pong buffers
        g_h16[i >> 5][(size_t)N_NODES * HID + (i & 31)] = __float2half(0.f);
    }
    if (i < N_SG + 2) g_normi[i] = 0;
}

// ---------------- launch 5: CSR fill (+ self loops)  AND  conv0 (fused) ----------------
#define FILL_B ((N_RAW + 255) / 256)         // 12891
#define CONV_B (N_NODES / 8)                 // 12500 (exact: all warps valid)
__global__ void __launch_bounds__(256) k_fill_conv0(const void* __restrict__ ei,
                                                    const float* __restrict__ x,
                                                    const float* __restrict__ W0,
                                                    const float* __restrict__ b0) {
    __shared__ float Wsm[IN_CH * HID];   // 16 KB (used by conv0 blocks only)
    __shared__ float bsm[HID];
    __shared__ int   wmax[8];
    if (blockIdx.x < FILL_B) {
        int i = blockIdx.x * blockDim.x + threadIdx.x;
        int* csr = (int*)g_csr4;
        if (i < N_EDGES) {
            int r = edge_at(ei, (size_t)i);               // src
            int c = edge_at(ei, (size_t)N_EDGES + i);     // dst
            int pos = atomicAdd(&g_cursor[c], 1);
            csr[min(max(pos, 0), N_PAD_MAX - 1)] = r;
        } else if (i < N_RAW) {
            int n = i - N_EDGES;
            int pos = atomicAdd(&g_cursor[n], 1);
            csr[min(max(pos, 0), N_PAD_MAX - 1)] = n;     // self loop
        }
        return;
    }
    // ---- conv0: raw_0 = dinv * (x @ W0 + b0), stored fp16; max -> g_normi[0] ----
    for (int i = threadIdx.x; i < IN_CH * HID; i += blockDim.x) Wsm[i] = W0[i];
    if (threadIdx.x < HID) bsm[threadIdx.x] = b0[threadIdx.x];
    __syncthreads();
    int node = (blockIdx.x - FILL_B) * 8 + (threadIdx.x >> 5);
    int wid  = threadIdx.x >> 5;
    int lane = threadIdx.x & 31;
    float xr[4];
#pragma unroll
    for (int q = 0; q < 4; q++) xr[q] = x[(size_t)node * IN_CH + q * 32 + lane];
    float y = bsm[lane];
#pragma unroll
    for (int q = 0; q < 4; q++)
#pragma unroll
        for (int c = 0; c < 32; c++) {
            float xv = __shfl_sync(0xffffffffu, xr[q], c);
            y = fmaf(xv, Wsm[(q * 32 + c) * HID + lane], y);
        }
    float sv = y * g_dinv[node];
    g_h16[0][(size_t)node * HID + lane] = __float2half(sv);
    // block-level exact max -> 1 atomic per block
    float m = fabsf(sv);
#pragma unroll
    for (int d = 16; d >= 1; d >>= 1) m = fmaxf(m, __shfl_xor_sync(0xffffffffu, m, d));
    if (lane == 0) wmax[wid] = __float_as_int(m);
    __syncthreads();
    if (threadIdx.x == 0) {
        int bm = wmax[0];
#pragma unroll
        for (int i = 1; i < 8; i++) bm = max(bm, wmax[i]);
        atomicMax(&g_normi[0], bm);
    }
}

// ---------------- launches 6..36: SG layer (fp16 state, fp32 math, renormalized) ----------------
// Lane layout: 8 groups (grp=lane>>2) x 4 subs (sub=lane&3). Group g handles edge g
// of each 8-edge chunk; thread reads 16B = 8 fp16 channels [sub*8 .. sub*8+7].
__device__ __forceinline__ int pick8(int4 s0, int4 s1, int grp) {
    int4 s = (grp & 4) ? s1 : s0;
    int m = grp & 3;
    return (m == 0) ? s.x : (m == 1) ? s.y : (m == 2) ? s.z : s.w;
}

__device__ __forceinline__ void acc_add(float2* A, uint4 v) {
    float2 f0 = __half22float2(*(__half2*)&v.x);
    float2 f1 = __half22float2(*(__half2*)&v.y);
    float2 f2 = __half22float2(*(__half2*)&v.z);
    float2 f3 = __half22float2(*(__half2*)&v.w);
    A[0].x += f0.x; A[0].y += f0.y;
    A[1].x += f1.x; A[1].y += f1.y;
    A[2].x += f2.x; A[2].y += f2.y;
    A[3].x += f3.x; A[3].y += f3.y;
}

__global__ void __launch_bounds__(256) k_sg_layer(int parity, int l,
                                                  const float* __restrict__ W,
                                                  const float* __restrict__ b) {
    __shared__ float Wsm[HID * HID];
    __shared__ float bsm[HID];
    __shared__ int   wmax[8];
    for (int i = threadIdx.x; i < HID * HID; i += blockDim.x) Wsm[i] = W[i];
    if (threadIdx.x < HID) bsm[threadIdx.x] = b[threadIdx.x];
    __syncthreads();
    int node = blockIdx.x * 8 + (threadIdx.x >> 5);
    int wid  = threadIdx.x >> 5;
    int lane = threadIdx.x & 31;

    // normalization scalars (parallel product over lanes; all uniform loads)
    float inv = 1.f / stage_max(l);
    float pm = (lane < l) ? stage_max(lane) : 1.f;
#pragma unroll
    for (int d = 16; d >= 1; d >>= 1) pm *= __shfl_xor_sync(0xffffffffu, pm, d);
    float cb = inv / pm;                  // Π_{j<=l} 1/M_j (bias scale)

    const uint4* __restrict__ hin = (const uint4*)g_h16[parity];  // row = 4 uint4
    __half* __restrict__ hout = g_h16[parity ^ 1];

    int e8   = g_offs[node] >> 3;     // segments padded to mult of 8
    int end8 = g_offs[node + 1] >> 3;
    const int grp = lane >> 2, sub = lane & 3;

    float2 A[4] = {{0.f,0.f},{0.f,0.f},{0.f,0.f},{0.f,0.f}};
    float2 B[4] = {{0.f,0.f},{0.f,0.f},{0.f,0.f},{0.f,0.f}};

    // 16 edges per iteration: 4 CSR quads, 2 independent gathers per thread
    for (; e8 + 2 <= end8; e8 += 2) {
        int4 s0 = __ldg(&g_csr4[2 * e8]);
        int4 s1 = __ldg(&g_csr4[2 * e8 + 1]);
        int4 s2 = __ldg(&g_csr4[2 * e8 + 2]);
        int4 s3 = __ldg(&g_csr4[2 * e8 + 3]);
        int srcA = pick8(s0, s1, grp);
        int srcB = pick8(s2, s3, grp);
        uint4 va = hin[srcA * 4 + sub];
        uint4 vb = hin[srcB * 4 + sub];
        acc_add(A, va);
        acc_add(B, vb);
    }
    if (e8 < end8) {
        int4 s0 = __ldg(&g_csr4[2 * e8]);
        int4 s1 = __ldg(&g_csr4[2 * e8 + 1]);
        int srcA = pick8(s0, s1, grp);
        uint4 va = hin[srcA * 4 + sub];
        acc_add(A, va);
    }
#pragma unroll
    for (int i = 0; i < 4; i++) { A[i].x += B[i].x; A[i].y += B[i].y; }

    // reduce across the 8 groups (strides 4,8,16 flip grp bits)
#pragma unroll
    for (int d = 4; d <= 16; d <<= 1) {
#pragma unroll
        for (int i = 0; i < 4; i++) {
            A[i].x += __shfl_xor_sync(0xffffffffu, A[i].x, d);
            A[i].y += __shfl_xor_sync(0xffffffffu, A[i].y, d);
        }
    }
    // channel c lives at lanes with sub==c>>3, component c&7; broadcast from lane c>>3.
    float y = 0.f;
#pragma unroll
    for (int c = 0; c < 32; c++) {
        float comp = ((c & 7) == 0) ? A[0].x : ((c & 7) == 1) ? A[0].y :
                     ((c & 7) == 2) ? A[1].x : ((c & 7) == 3) ? A[1].y :
                     ((c & 7) == 4) ? A[2].x : ((c & 7) == 5) ? A[2].y :
                     ((c & 7) == 6) ? A[3].x : A[3].y;
        float v = __shfl_sync(0xffffffffu, comp, c >> 3);
        y = fmaf(v, Wsm[c * HID + lane], y);
    }
    float dv = g_dinv[node];
    float t = fmaf(y, dv * inv, cb * bsm[lane]);
    float sv = fmaxf(t, 0.f) * dv;                 // pre-scale for next layer
    hout[node * HID + lane] = __float2half(sv);

    // block-level exact max -> 1 atomic per block
    float m = sv;
#pragma unroll
    for (int d = 16; d >= 1; d >>= 1) m = fmaxf(m, __shfl_xor_sync(0xffffffffu, m, d));
    if (lane == 0) wmax[wid] = __float_as_int(m);
    __syncthreads();
    if (threadIdx.x == 0) {
        int bm = wmax[0];
#pragma unroll
        for (int i = 1; i < 8; i++) bm = max(bm, wmax[i]);
        atomicMax(&g_normi[l + 1], bm);
    }
}

// ---------------- final launch: out = h @ W32 + b32 ----------------
// true h'_31 = raw_31 * Π_{j=0..30} M_j; unscale h' by sqrt(deg).
__global__ void k_conv_out(int parity, const float* __restrict__ W32,
                           const float* __restrict__ b32, float* __restrict__ out) {
    __shared__ float Wsm[HID * OUT_CH];  // 8 KB
    __shared__ float bsm[OUT_CH];
    for (int i = threadIdx.x; i < HID * OUT_CH; i += blockDim.x) Wsm[i] = W32[i];
    if (threadIdx.x < OUT_CH) bsm[threadIdx.x] = b32[threadIdx.x];
    __syncthreads();
    int node = blockIdx.x * 8 + (threadIdx.x >> 5);
    int lane = threadIdx.x & 31;
    // parallel product of M_0..M_30
    float pm = (lane < N_SG) ? stage_max(lane) : 1.f;
#pragma unroll
    for (int d = 16; d >= 1; d >>= 1) pm *= __shfl_xor_sync(0xffffffffu, pm, d);
    float hv = __half2float(g_h16[parity][(size_t)node * HID + lane])
               * pm * sqrtf((float)g_deg[node]);
    float y0 = bsm[lane], y1 = bsm[lane + 32];
#pragma unroll
    for (int c = 0; c < 32; c++) {
        float a = __shfl_sync(0xffffffffu, hv, c);
        y0 = fmaf(a, Wsm[c * OUT_CH + lane], y0);
        y1 = fmaf(a, Wsm[c * OUT_CH + lane + 32], y1);
    }
    out[(size_t)node * OUT_CH + lane]      = y0;
    out[(size_t)node * OUT_CH + lane + 32] = y1;
}

// ---------------- launch ----------------
extern "C" void kernel_launch(void* const* d_in, const int* in_sizes, int n_in,
                              void* d_out, int out_size) {
    const float* x = nullptr; const float* W0 = nullptr; const float* b0 = nullptr;
    const float* Ws = nullptr; const float* bs = nullptr;
    const float* W32 = nullptr; const float* b32 = nullptr;
    const void* ei = nullptr;
    for (int i = 0; i < n_in; i++) {
        switch (in_sizes[i]) {
            case 12800000: x   = (const float*)d_in[i]; break;
            case 4096:     W0  = (const float*)d_in[i]; break;
            case 32:       b0  = (const float*)d_in[i]; break;
            case 31744:    Ws  = (const float*)d_in[i]; break;
            case 992:      bs  = (const float*)d_in[i]; break;
            case 2048:     W32 = (const float*)d_in[i]; break;
            case 64:       b32 = (const float*)d_in[i]; break;
            case 6400000:  ei  = d_in[i]; break;
            default: break;
        }
    }
    if (!x || !W0 || !b0 || !Ws || !bs || !W32 || !b32 || !ei) return;

    float* out = (float*)d_out;
    const int T = 256;

    k_detect_init<<<(N_NODES + T - 1) / T, T>>>((const int*)ei);          // 1
    k_deg_accum<<<(N_EDGES + T - 1) / T, T>>>(ei);                        // 2
    k_scan_dinv<<<1, 1024>>>();                                           // 3
    k_prep<<<(N_PAD_MAX / 4 + T - 1) / T, T>>>();                         // 4
    k_fill_conv0<<<FILL_B + CONV_B, T>>>(ei, x, W0, b0);                  // 5

    int parity = 0;
    for (int l = 0; l < N_SG; l++) {                                      // 6..36
        k_sg_layer<<<CONV_B, T>>>(parity, l, Ws + (size_t)l * HID * HID, bs + (size_t)l * HID);
        parity ^= 1;
    }

    k_conv_out<<<CONV_B, T>>>(parity, W32, b32, out);                     // 37
}

// round 13
// speedup vs baseline: 1.6784x; 1.0584x over previous
#include <cuda_runtime.h>
#include <cuda_bf16.h>
#include <cstdint>

#define N_NODES 100000
#define N_EDGES 3200000
#define IN_CH   128
#define HID     32
#define OUT_CH  64
#define N_SG    31
#define N_RAW   (N_EDGES + N_NODES)          // edges + self loops (unpadded)
#define N_PAD_MAX (N_EDGES + 4 * N_NODES)    // padded CSR capacity (3.6M, mult of 4)

#define PG      592                          // persistent grid: 148 SMs x 4 blocks
#define PWARPS  (PG * 8)                     // 4736 node-warps

// ---------------- device scratch (static globals; no allocation) ----------------
__device__ int    g_is64;
__device__ int    g_deg[N_NODES];
__device__ float  g_dinv[N_NODES];
__device__ int    g_offs[N_NODES + 1];
__device__ int    g_cursor[N_NODES];
__device__ int4   g_csr4[N_PAD_MAX / 4];             // src indices, padded w/ sentinel N_NODES
__device__ float4 g_h[2][(size_t)(N_NODES + 1) * 8]; // ping-pong state (row N_NODES = zeros)
// grid barrier state (reset by k_prep each call)
__device__ unsigned          g_count[N_SG];          // per-phase arrival counters
__device__ volatile unsigned g_gen;                  // release generation

// Safe edge accessor: idx in [0, 2*N_EDGES)
__device__ __forceinline__ int edge_at(const void* ei, size_t idx) {
    int v = g_is64 ? (int)((const long long*)ei)[idx]
                   : ((const int*)ei)[idx];
    return min(max(v, 0), N_NODES - 1);
}

// ---------------- launch 1: dtype detect + deg init ----------------
__global__ void k_detect_init(const int* __restrict__ w) {
    int i = blockIdx.x * blockDim.x + threadIdx.x;
    if (i < N_NODES) g_deg[i] = 1;  // self loop
    if (blockIdx.x == 0) {
        __shared__ int any_nonzero;
        if (threadIdx.x == 0) any_nonzero = 0;
        __syncthreads();
        size_t pos = (size_t)threadIdx.x * 24994 + 1;   // tid<256 -> max 6.37M
        if (w[pos] != 0) any_nonzero = 1;
        __syncthreads();
        if (threadIdx.x == 0) g_is64 = any_nonzero ? 0 : 1;
    }
}

// ---------------- launch 2: degree accumulation ----------------
__global__ void k_deg_accum(const void* __restrict__ ei) {
    int i = blockIdx.x * blockDim.x + threadIdx.x;
    if (i < N_EDGES) {
        int c = edge_at(ei, (size_t)N_EDGES + i);   // col = edge_index[1] (dst)
        atomicAdd(&g_deg[c], 1);
    }
}

// ---------------- launch 3: dinv + padded exclusive scan + cursor init ----------------
__global__ void k_scan_dinv() {
    __shared__ int part[1024];
    const int tid = threadIdx.x;
    const int chunk = (N_NODES + 1023) / 1024;
    int beg = tid * chunk;
    int end = min(beg + chunk, N_NODES);
    int s = 0;
    for (int i = beg; i < end; i++) {
        int d = g_deg[i];
        g_dinv[i] = rsqrtf((float)d);
        s += (d + 3) & ~3;                      // pad each segment to mult of 4
    }
    part[tid] = s;
    __syncthreads();
    for (int off = 1; off < 1024; off <<= 1) {
        int v = (tid >= off) ? part[tid - off] : 0;
        __syncthreads();
        part[tid] += v;
        __syncthreads();
    }
    int run = (tid == 0) ? 0 : part[tid - 1];
    for (int i = beg; i < end; i++) {
        g_offs[i] = run;
        g_cursor[i] = run;
        run += (g_deg[i] + 3) & ~3;
    }
    if (tid == 1023) g_offs[N_NODES] = run;
}

// ---------------- launch 4: CSR sentinel fill + zero sentinel h rows + barrier reset ----------------
__global__ void k_prep() {
    int i = blockIdx.x * blockDim.x + threadIdx.x;
    if (i < N_PAD_MAX / 4) g_csr4[i] = make_int4(N_NODES, N_NODES, N_NODES, N_NODES);
    if (i < 64) {  // zero row N_NODES of both ping-pong buffers
        ((float*)g_h[i >> 5])[(size_t)N_NODES * 32 + (i & 31)] = 0.f;
    }
    if (i < N_SG) g_count[i] = 0u;
    if (i == N_SG) g_gen = 0u;
}

// ---------------- launch 5: CSR fill (+ self loops)  AND  conv0 (fused) ----------------
#define FILL_B ((N_RAW + 255) / 256)         // 12891
#define CONV_B ((N_NODES + 7) / 8)           // 12500
__global__ void __launch_bounds__(256) k_fill_conv0(const void* __restrict__ ei,
                                                    const float* __restrict__ x,
                                                    const float* __restrict__ W0,
                                                    const float* __restrict__ b0) {
    __shared__ float Wsm[IN_CH * HID];   // 16 KB (used by conv0 blocks only)
    __shared__ float bsm[HID];
    if (blockIdx.x < FILL_B) {
        int i = blockIdx.x * blockDim.x + threadIdx.x;
        int* csr = (int*)g_csr4;
        if (i < N_EDGES) {
            int r = edge_at(ei, (size_t)i);               // src
            int c = edge_at(ei, (size_t)N_EDGES + i);     // dst
            int pos = atomicAdd(&g_cursor[c], 1);
            csr[min(max(pos, 0), N_PAD_MAX - 1)] = r;
        } else if (i < N_RAW) {
            int n = i - N_EDGES;
            int pos = atomicAdd(&g_cursor[n], 1);
            csr[min(max(pos, 0), N_PAD_MAX - 1)] = n;     // self loop
        }
        return;
    }
    // ---- conv0: h'0 = dinv * (x @ W0 + b0) ----
    for (int i = threadIdx.x; i < IN_CH * HID; i += blockDim.x) Wsm[i] = W0[i];
    if (threadIdx.x < HID) bsm[threadIdx.x] = b0[threadIdx.x];
    __syncthreads();
    int node = (blockIdx.x - FILL_B) * 8 + (threadIdx.x >> 5);
    int lane = threadIdx.x & 31;
    if (node >= N_NODES) return;
    float xr[4];
#pragma unroll
    for (int q = 0; q < 4; q++) xr[q] = x[(size_t)node * IN_CH + q * 32 + lane];
    float y = bsm[lane];
#pragma unroll
    for (int q = 0; q < 4; q++)
#pragma unroll
        for (int c = 0; c < 32; c++) {
            float xv = __shfl_sync(0xffffffffu, xr[q], c);
            y = fmaf(xv, Wsm[(q * 32 + c) * HID + lane], y);
        }
    ((float*)g_h[0])[(size_t)node * 32 + lane] = y * g_dinv[node];
}

// ---------------- launch 6: persistent — 31 SG layers + conv_out ----------------
// Grid barrier: per-phase counter + generation release. All PG blocks co-resident
// (__launch_bounds__(256,4): <=64 regs, ~8.5KB smem -> 4 blocks/SM guaranteed).
__device__ __forceinline__ void grid_barrier(int phase) {
    __syncthreads();
    if (threadIdx.x == 0) {
        __threadfence();
        unsigned t = atomicAdd(&g_count[phase], 1u);
        if (t == PG - 1u) {
            __threadfence();
            g_gen = (unsigned)(phase + 1);
        } else {
            while (g_gen < (unsigned)(phase + 1)) __nanosleep(64);
        }
        __threadfence();
    }
    __syncthreads();
}

__device__ __forceinline__ int pick_lane4(int4 s, int grp) {
    return (grp == 0) ? s.x : (grp == 1) ? s.y : (grp == 2) ? s.z : s.w;
}

__global__ void __launch_bounds__(256, 4) k_layers(const float* __restrict__ Ws,
                                                   const float* __restrict__ bs,
                                                   const float* __restrict__ W32,
                                                   const float* __restrict__ b32,
                                                   float* __restrict__ out) {
    __shared__ float Wbuf[HID * OUT_CH];   // 8KB: holds W_l (4KB) or W32 (8KB)
    __shared__ float bbuf[OUT_CH];
    const int wid  = threadIdx.x >> 5;
    const int lane = threadIdx.x & 31;
    const int gwarp = blockIdx.x * 8 + wid;
    const int grp = lane >> 3, sub = lane & 7;

    int parity = 0;
    for (int l = 0; l < N_SG; l++) {
        // load this layer's weights (block-local)
        for (int i = threadIdx.x; i < HID * HID; i += 256) Wbuf[i] = Ws[l * HID * HID + i];
        if (threadIdx.x < HID) bbuf[threadIdx.x] = bs[l * HID + threadIdx.x];
        __syncthreads();

        const float4* __restrict__ hin = g_h[parity];
        float* __restrict__ hout = (float*)g_h[parity ^ 1];

        for (int node = gwarp; node < N_NODES; node += PWARPS) {
            int e4   = g_offs[node] >> 2;
            int end4 = g_offs[node + 1] >> 2;

            float4 accA = make_float4(0.f, 0.f, 0.f, 0.f);
            float4 accB = make_float4(0.f, 0.f, 0.f, 0.f);
            for (; e4 + 2 <= end4; e4 += 2) {
                int4 sA = __ldg(&g_csr4[e4]);
                int4 sB = __ldg(&g_csr4[e4 + 1]);
                int srcA = pick_lane4(sA, grp);
                int srcB = pick_lane4(sB, grp);
                float4 vA = hin[srcA * 8 + sub];
                float4 vB = hin[srcB * 8 + sub];
                accA.x += vA.x; accA.y += vA.y; accA.z += vA.z; accA.w += vA.w;
                accB.x += vB.x; accB.y += vB.y; accB.z += vB.z; accB.w += vB.w;
            }
            if (e4 < end4) {
                int4 sA = __ldg(&g_csr4[e4]);
                int srcA = pick_lane4(sA, grp);
                float4 vA = hin[srcA * 8 + sub];
                accA.x += vA.x; accA.y += vA.y; accA.z += vA.z; accA.w += vA.w;
            }
            accA.x += accB.x; accA.y += accB.y; accA.z += accB.z; accA.w += accB.w;

            // reduce across the 4 lane groups
#pragma unroll
            for (int d = 8; d <= 16; d <<= 1) {
                accA.x += __shfl_xor_sync(0xffffffffu, accA.x, d);
                accA.y += __shfl_xor_sync(0xffffffffu, accA.y, d);
                accA.z += __shfl_xor_sync(0xffffffffu, accA.z, d);
                accA.w += __shfl_xor_sync(0xffffffffu, accA.w, d);
            }
            // remap: channel==lane held at lane lane>>2, component lane&3
            float a0 = __shfl_sync(0xffffffffu, accA.x, lane >> 2);
            float a1 = __shfl_sync(0xffffffffu, accA.y, lane >> 2);
            float a2 = __shfl_sync(0xffffffffu, accA.z, lane >> 2);
            float a3 = __shfl_sync(0xffffffffu, accA.w, lane >> 2);
            int m = lane & 3;
            float agg = (m == 0) ? a0 : (m == 1) ? a1 : (m == 2) ? a2 : a3;

            float dv = g_dinv[node];
            agg *= dv;

            float y = bbuf[lane];
#pragma unroll
            for (int c = 0; c < 32; c++)
                y = fmaf(__shfl_sync(0xffffffffu, agg, c), Wbuf[c * HID + lane], y);
            hout[node * 32 + lane] = fmaxf(y, 0.f) * dv;   // pre-scale for next layer
        }

        if (l < N_SG - 1) grid_barrier(l);
        parity ^= 1;
    }

    // ---- conv_out fused (same node->warp mapping as last layer: no global sync needed) ----
    __syncthreads();   // everyone in block done reading Wbuf of layer 30
    for (int i = threadIdx.x; i < HID * OUT_CH; i += 256) Wbuf[i] = W32[i];
    if (threadIdx.x < OUT_CH) bbuf[threadIdx.x] = b32[threadIdx.x];
    __syncthreads();
    const float* __restrict__ hfin = (const float*)g_h[parity];
    for (int node = gwarp; node < N_NODES; node += PWARPS) {
        float hv = hfin[(size_t)node * 32 + lane] * sqrtf((float)g_deg[node]);
        float y0 = bbuf[lane], y1 = bbuf[lane + 32];
#pragma unroll
        for (int c = 0; c < 32; c++) {
            float a = __shfl_sync(0xffffffffu, hv, c);
            y0 = fmaf(a, Wbuf[c * OUT_CH + lane], y0);
            y1 = fmaf(a, Wbuf[c * OUT_CH + lane + 32], y1);
        }
        out[(size_t)node * OUT_CH + lane]      = y0;
        out[(size_t)node * OUT_CH + lane + 32] = y1;
    }
}

// ---------------- launch ----------------
extern "C" void kernel_launch(void* const* d_in, const int* in_sizes, int n_in,
                              void* d_out, int out_size) {
    const float* x = nullptr; const float* W0 = nullptr; const float* b0 = nullptr;
    const float* Ws = nullptr; const float* bs = nullptr;
    const float* W32 = nullptr; const float* b32 = nullptr;
    const void* ei = nullptr;
    for (int i = 0; i < n_in; i++) {
        switch (in_sizes[i]) {
            case 12800000: x   = (const float*)d_in[i]; break;
            case 4096:     W0  = (const float*)d_in[i]; break;
            case 32:       b0  = (const float*)d_in[i]; break;
            case 31744:    Ws  = (const float*)d_in[i]; break;
            case 992:      bs  = (const float*)d_in[i]; break;
            case 2048:     W32 = (const float*)d_in[i]; break;
            case 64:       b32 = (const float*)d_in[i]; break;
            case 6400000:  ei  = d_in[i]; break;
            default: break;
        }
    }
    if (!x || !W0 || !b0 || !Ws || !bs || !W32 || !b32 || !ei) return;

    float* out = (float*)d_out;
    const int T = 256;

    k_detect_init<<<(N_NODES + T - 1) / T, T>>>((const int*)ei);          // 1
    k_deg_accum<<<(N_EDGES + T - 1) / T, T>>>(ei);                        // 2
    k_scan_dinv<<<1, 1024>>>();                                           // 3
    k_prep<<<(N_PAD_MAX / 4 + T - 1) / T, T>>>();                         // 4
    k_fill_conv0<<<FILL_B + CONV_B, T>>>(ei, x, W0, b0);                  // 5
    k_layers<<<PG, T>>>(Ws, bs, W32, b32, out);                           // 6
}

// round 14
// speedup vs baseline: 1.6958x; 1.0104x over previous
#include <cuda_runtime.h>
#include <cuda_bf16.h>
#include <cstdint>

#define N_NODES 100000
#define N_EDGES 3200000
#define IN_CH   128
#define HID     32
#define OUT_CH  64
#define N_SG    31
#define N_RAW   (N_EDGES + N_NODES)          // edges + self loops (unpadded)
#define N_PAD_MAX (N_EDGES + 4 * N_NODES)    // padded CSR capacity (3.6M, mult of 4)

#define PG      888                          // persistent grid: 148 SMs x 6 blocks
#define PWARPS  (PG * 8)                     // 7104 node-warps

// ---------------- device scratch (static globals; no allocation) ----------------
__device__ int    g_is64;
__device__ int    g_deg[N_NODES];
__device__ float  g_dinv[N_NODES];
__device__ int    g_offs[N_NODES + 1];
__device__ int    g_cursor[N_NODES];
__device__ int4   g_csr4[N_PAD_MAX / 4];             // src indices, padded w/ sentinel N_NODES
__device__ float4 g_h[2][(size_t)(N_NODES + 1) * 8]; // ping-pong state (row N_NODES = zeros)
// grid barrier state (reset by k_init each call)
__device__ unsigned          g_count[N_SG + 1];      // per-phase arrival counters
__device__ volatile unsigned g_gen;                  // release generation

// Safe edge accessor: idx in [0, 2*N_EDGES)
__device__ __forceinline__ int edge_at(const void* ei, size_t idx) {
    int v = g_is64 ? (int)((const long long*)ei)[idx]
                   : ((const int*)ei)[idx];
    return min(max(v, 0), N_NODES - 1);
}

// ---------------- launch 1: dtype detect + deg init + CSR sentinels + barrier reset ----------------
__global__ void k_init(const int* __restrict__ w) {
    int i = blockIdx.x * blockDim.x + threadIdx.x;
    if (i < N_NODES) g_deg[i] = 1;  // self loop
    if (i < N_PAD_MAX / 4) g_csr4[i] = make_int4(N_NODES, N_NODES, N_NODES, N_NODES);
    if (i < 64) {  // zero row N_NODES of both ping-pong buffers
        ((float*)g_h[i >> 5])[(size_t)N_NODES * 32 + (i & 31)] = 0.f;
    }
    if (i < N_SG + 1) g_count[i] = 0u;
    if (i == N_SG + 1) g_gen = 0u;
    if (blockIdx.x == 0) {
        __shared__ int any_nonzero;
        if (threadIdx.x == 0) any_nonzero = 0;
        __syncthreads();
        // sample odd int32 words over [0, 6.4M): all-zero <=> int64 payload
        size_t pos = (size_t)threadIdx.x * 24994 + 1;   // tid<256 -> max 6.37M
        if (w[pos] != 0) any_nonzero = 1;
        __syncthreads();
        if (threadIdx.x == 0) g_is64 = any_nonzero ? 0 : 1;
    }
}

// ---------------- launch 2: degree accumulation ----------------
__global__ void k_deg_accum(const void* __restrict__ ei) {
    int i = blockIdx.x * blockDim.x + threadIdx.x;
    if (i < N_EDGES) {
        int c = edge_at(ei, (size_t)N_EDGES + i);   // col = edge_index[1] (dst)
        atomicAdd(&g_deg[c], 1);
    }
}

// ---------------- launch 3: dinv + padded exclusive scan + cursor init ----------------
__global__ void k_scan_dinv() {
    __shared__ int part[1024];
    const int tid = threadIdx.x;
    const int chunk = (N_NODES + 1023) / 1024;
    int beg = tid * chunk;
    int end = min(beg + chunk, N_NODES);
    int s = 0;
    for (int i = beg; i < end; i++) {
        int d = g_deg[i];
        g_dinv[i] = rsqrtf((float)d);
        s += (d + 3) & ~3;                      // pad each segment to mult of 4
    }
    part[tid] = s;
    __syncthreads();
    for (int off = 1; off < 1024; off <<= 1) {
        int v = (tid >= off) ? part[tid - off] : 0;
        __syncthreads();
        part[tid] += v;
        __syncthreads();
    }
    int run = (tid == 0) ? 0 : part[tid - 1];
    for (int i = beg; i < end; i++) {
        g_offs[i] = run;
        g_cursor[i] = run;
        run += (g_deg[i] + 3) & ~3;
    }
    if (tid == 1023) g_offs[N_NODES] = run;
}

// ---------------- launch 4: persistent mega-kernel ----------------
// phase A: CSR fill + conv0 (independent); barrier; 31 SG layers; conv_out.
// All PG blocks co-resident: __launch_bounds__(256,6) -> regs<=42, smem 16.3KB*6=98KB/SM.
__device__ __forceinline__ void grid_barrier(int phase) {
    __syncthreads();
    if (threadIdx.x == 0) {
        __threadfence();
        unsigned t = atomicAdd(&g_count[phase], 1u);
        if (t == PG - 1u) {
            __threadfence();
            g_gen = (unsigned)(phase + 1);
        } else {
            while (g_gen < (unsigned)(phase + 1)) __nanosleep(64);
        }
        __threadfence();
    }
    __syncthreads();
}

__device__ __forceinline__ int pick_lane4(int4 s, int grp) {
    return (grp == 0) ? s.x : (grp == 1) ? s.y : (grp == 2) ? s.z : s.w;
}

__global__ void __launch_bounds__(256, 6) k_mega(const void* __restrict__ ei,
                                                 const float* __restrict__ x,
                                                 const float* __restrict__ W0,
                                                 const float* __restrict__ b0,
                                                 const float* __restrict__ Ws,
                                                 const float* __restrict__ bs,
                                                 const float* __restrict__ W32,
                                                 const float* __restrict__ b32,
                                                 float* __restrict__ out) {
    __shared__ float Wbuf[IN_CH * HID];    // 16KB: W0 / W_l / W32
    __shared__ float bbuf[OUT_CH];
    const int tid  = threadIdx.x;
    const int wid  = tid >> 5;
    const int lane = tid & 31;
    const int gwarp = blockIdx.x * 8 + wid;
    const int grp = lane >> 3, sub = lane & 7;

    // ---- phase A1: CSR fill (grid-stride over edges + self loops) ----
    {
        int* csr = (int*)g_csr4;
        for (int i = blockIdx.x * 256 + tid; i < N_RAW; i += PG * 256) {
            if (i < N_EDGES) {
                int r = edge_at(ei, (size_t)i);               // src
                int c = edge_at(ei, (size_t)N_EDGES + i);     // dst
                int pos = atomicAdd(&g_cursor[c], 1);
                csr[min(max(pos, 0), N_PAD_MAX - 1)] = r;
            } else {
                int n = i - N_EDGES;
                int pos = atomicAdd(&g_cursor[n], 1);
                csr[min(max(pos, 0), N_PAD_MAX - 1)] = n;     // self loop
            }
        }
    }

    // ---- phase A2: conv0 h'0 = dinv * (x @ W0 + b0) ----
    for (int i = tid; i < IN_CH * HID; i += 256) Wbuf[i] = W0[i];
    if (tid < HID) bbuf[tid] = b0[tid];
    __syncthreads();
    for (int node = gwarp; node < N_NODES; node += PWARPS) {
        float xr[4];
#pragma unroll
        for (int q = 0; q < 4; q++) xr[q] = x[(size_t)node * IN_CH + q * 32 + lane];
        float y = bbuf[lane];
#pragma unroll
        for (int q = 0; q < 4; q++)
#pragma unroll
            for (int c = 0; c < 32; c++) {
                float xv = __shfl_sync(0xffffffffu, xr[q], c);
                y = fmaf(xv, Wbuf[(q * 32 + c) * HID + lane], y);
            }
        ((float*)g_h[0])[(size_t)node * 32 + lane] = y * g_dinv[node];
    }

    grid_barrier(0);

    // ---- 31 SG layers ----
    int parity = 0;
    for (int l = 0; l < N_SG; l++) {
        for (int i = tid; i < HID * HID; i += 256) Wbuf[i] = Ws[l * HID * HID + i];
        if (tid < HID) bbuf[tid] = bs[l * HID + tid];
        __syncthreads();

        const float4* __restrict__ hin = g_h[parity];
        float* __restrict__ hout = (float*)g_h[parity ^ 1];

        for (int node = gwarp; node < N_NODES; node += PWARPS) {
            int e4   = g_offs[node] >> 2;
            int end4 = g_offs[node + 1] >> 2;

            float4 accA = make_float4(0.f, 0.f, 0.f, 0.f);
            float4 accB = make_float4(0.f, 0.f, 0.f, 0.f);
            for (; e4 + 2 <= end4; e4 += 2) {
                int4 sA = __ldg(&g_csr4[e4]);
                int4 sB = __ldg(&g_csr4[e4 + 1]);
                int srcA = pick_lane4(sA, grp);
                int srcB = pick_lane4(sB, grp);
                float4 vA = hin[srcA * 8 + sub];
                float4 vB = hin[srcB * 8 + sub];
                accA.x += vA.x; accA.y += vA.y; accA.z += vA.z; accA.w += vA.w;
                accB.x += vB.x; accB.y += vB.y; accB.z += vB.z; accB.w += vB.w;
            }
            if (e4 < end4) {
                int4 sA = __ldg(&g_csr4[e4]);
                int srcA = pick_lane4(sA, grp);
                float4 vA = hin[srcA * 8 + sub];
                accA.x += vA.x; accA.y += vA.y; accA.z += vA.z; accA.w += vA.w;
            }
            accA.x += accB.x; accA.y += accB.y; accA.z += accB.z; accA.w += accB.w;

            // reduce across the 4 lane groups
#pragma unroll
            for (int d = 8; d <= 16; d <<= 1) {
                accA.x += __shfl_xor_sync(0xffffffffu, accA.x, d);
                accA.y += __shfl_xor_sync(0xffffffffu, accA.y, d);
                accA.z += __shfl_xor_sync(0xffffffffu, accA.z, d);
                accA.w += __shfl_xor_sync(0xffffffffu, accA.w, d);
            }
            // remap: channel==lane held at lane lane>>2, component lane&3
            float a0 = __shfl_sync(0xffffffffu, accA.x, lane >> 2);
            float a1 = __shfl_sync(0xffffffffu, accA.y, lane >> 2);
            float a2 = __shfl_sync(0xffffffffu, accA.z, lane >> 2);
            float a3 = __shfl_sync(0xffffffffu, accA.w, lane >> 2);
            int m = lane & 3;
            float agg = (m == 0) ? a0 : (m == 1) ? a1 : (m == 2) ? a2 : a3;

            float dv = g_dinv[node];
            agg *= dv;

            float y = bbuf[lane];
#pragma unroll
            for (int c = 0; c < 32; c++)
                y = fmaf(__shfl_sync(0xffffffffu, agg, c), Wbuf[c * HID + lane], y);
            hout[node * 32 + lane] = fmaxf(y, 0.f) * dv;   // pre-scale for next layer
        }

        if (l < N_SG - 1) grid_barrier(l + 1);
        parity ^= 1;
    }

    // ---- conv_out (same node->warp mapping as layers: no global sync needed) ----
    __syncthreads();
    for (int i = tid; i < HID * OUT_CH; i += 256) Wbuf[i] = W32[i];
    if (tid < OUT_CH) bbuf[tid] = b32[tid];
    __syncthreads();
    const float* __restrict__ hfin = (const float*)g_h[parity];
    for (int node = gwarp; node < N_NODES; node += PWARPS) {
        float hv = hfin[(size_t)node * 32 + lane] * sqrtf((float)g_deg[node]);
        float y0 = bbuf[lane], y1 = bbuf[lane + 32];
#pragma unroll
        for (int c = 0; c < 32; c++) {
            float a = __shfl_sync(0xffffffffu, hv, c);
            y0 = fmaf(a, Wbuf[c * OUT_CH + lane], y0);
            y1 = fmaf(a, Wbuf[c * OUT_CH + lane + 32], y1);
        }
        out[(size_t)node * OUT_CH + lane]      = y0;
        out[(size_t)node * OUT_CH + lane + 32] = y1;
    }
}

// ---------------- launch ----------------
extern "C" void kernel_launch(void* const* d_in, const int* in_sizes, int n_in,
                              void* d_out, int out_size) {
    const float* x = nullptr; const float* W0 = nullptr; const float* b0 = nullptr;
    const float* Ws = nullptr; const float* bs = nullptr;
    const float* W32 = nullptr; const float* b32 = nullptr;
    const void* ei = nullptr;
    for (int i = 0; i < n_in; i++) {
        switch (in_sizes[i]) {
            case 12800000: x   = (const float*)d_in[i]; break;
            case 4096:     W0  = (const float*)d_in[i]; break;
            case 32:       b0  = (const float*)d_in[i]; break;
            case 31744:    Ws  = (const float*)d_in[i]; break;
            case 992:      bs  = (const float*)d_in[i]; break;
            case 2048:     W32 = (const float*)d_in[i]; break;
            case 64:       b32 = (const float*)d_in[i]; break;
            case 6400000:  ei  = d_in[i]; break;
            default: break;
        }
    }
    if (!x || !W0 || !b0 || !Ws || !bs || !W32 || !b32 || !ei) return;

    float* out = (float*)d_out;
    const int T = 256;
    const int INIT_B = (N_PAD_MAX / 4 + T - 1) / T;   // covers all init ranges

    k_init<<<INIT_B, T>>>((const int*)ei);                                // 1
    k_deg_accum<<<(N_EDGES + T - 1) / T, T>>>(ei);                        // 2
    k_scan_dinv<<<1, 1024>>>();                                           // 3
    k_mega<<<PG, T>>>(ei, x, W0, b0, Ws, bs, W32, b32, out);              // 4
}

// round 16
// speedup vs baseline: 1.7728x; 1.0454x over previous
#include <cuda_runtime.h>
#include <cuda_bf16.h>
#include <cstdint>

#define N_NODES 100000
#define N_EDGES 3200000
#define IN_CH   128
#define HID     32
#define OUT_CH  64
#define N_SG    31
#define N_RAW   (N_EDGES + N_NODES)          // edges + self loops (unpadded)
#define N_PAD_MAX (N_EDGES + 4 * N_NODES)    // padded CSR capacity (3.6M, mult of 4)

// ---------------- device scratch (static globals; no allocation) ----------------
__device__ int    g_is64;
__device__ int    g_deg[N_NODES];
__device__ float  g_dinv[N_NODES];
__device__ int    g_offs[N_NODES + 1];
__device__ int    g_cursor[N_NODES];
__device__ int4   g_csr4[N_PAD_MAX / 4];             // src indices, padded w/ sentinel N_NODES
__device__ float4 g_h[2][(size_t)(N_NODES + 1) * 8]; // ping-pong state (row N_NODES = zeros)

// Safe edge accessor: idx in [0, 2*N_EDGES)
__device__ __forceinline__ int edge_at(const void* ei, size_t idx) {
    int v = g_is64 ? (int)((const long long*)ei)[idx]
                   : ((const int*)ei)[idx];
    return min(max(v, 0), N_NODES - 1);
}

// ---------------- launch 1: dtype detect + deg init ----------------
__global__ void k_detect_init(const int* __restrict__ w) {
    int i = blockIdx.x * blockDim.x + threadIdx.x;
    if (i < N_NODES) g_deg[i] = 1;  // self loop
    if (blockIdx.x == 0) {
        __shared__ int any_nonzero;
        if (threadIdx.x == 0) any_nonzero = 0;
        __syncthreads();
        size_t pos = (size_t)threadIdx.x * 24994 + 1;   // tid<256 -> max 6.37M
        if (w[pos] != 0) any_nonzero = 1;
        __syncthreads();
        if (threadIdx.x == 0) g_is64 = any_nonzero ? 0 : 1;
    }
}

// ---------------- launch 2: degree accumulation ----------------
__global__ void k_deg_accum(const void* __restrict__ ei) {
    int i = blockIdx.x * blockDim.x + threadIdx.x;
    if (i < N_EDGES) {
        int c = edge_at(ei, (size_t)N_EDGES + i);   // col = edge_index[1] (dst)
        atomicAdd(&g_deg[c], 1);
    }
}

// ---------------- launch 3: dinv + padded exclusive scan + cursor init ----------------
__global__ void k_scan_dinv() {
    __shared__ int part[1024];
    const int tid = threadIdx.x;
    const int chunk = (N_NODES + 1023) / 1024;
    int beg = tid * chunk;
    int end = min(beg + chunk, N_NODES);
    int s = 0;
    for (int i = beg; i < end; i++) {
        int d = g_deg[i];
        g_dinv[i] = rsqrtf((float)d);
        s += (d + 3) & ~3;                      // pad each segment to mult of 4
    }
    part[tid] = s;
    __syncthreads();
    for (int off = 1; off < 1024; off <<= 1) {
        int v = (tid >= off) ? part[tid - off] : 0;
        __syncthreads();
        part[tid] += v;
        __syncthreads();
    }
    int run = (tid == 0) ? 0 : part[tid - 1];
    for (int i = beg; i < end; i++) {
        g_offs[i] = run;
        g_cursor[i] = run;
        run += (g_deg[i] + 3) & ~3;
    }
    if (tid == 1023) g_offs[N_NODES] = run;
}

// ---------------- launch 4: CSR sentinel fill + zero sentinel h rows ----------------
__global__ void k_prep() {
    int i = blockIdx.x * blockDim.x + threadIdx.x;
    if (i < N_PAD_MAX / 4) g_csr4[i] = make_int4(N_NODES, N_NODES, N_NODES, N_NODES);
    if (i < 64) {  // zero row N_NODES of both ping-pong buffers
        ((float*)g_h[i >> 5])[(size_t)N_NODES * 32 + (i & 31)] = 0.f;
    }
}

// ---------------- launch 5: CSR fill (+ self loops)  AND  conv0 (fused) ----------------
#define FILL_B ((N_RAW + 255) / 256)         // 12891
#define CONV_B ((N_NODES + 7) / 8)           // 12500
__global__ void __launch_bounds__(256) k_fill_conv0(const void* __restrict__ ei,
                                                    const float* __restrict__ x,
                                                    const float* __restrict__ W0,
                                                    const float* __restrict__ b0) {
    __shared__ float Wsm[IN_CH * HID];   // 16 KB (used by conv0 blocks only)
    __shared__ float bsm[HID];
    if (blockIdx.x < FILL_B) {
        int i = blockIdx.x * blockDim.x + threadIdx.x;
        int* csr = (int*)g_csr4;
        if (i < N_EDGES) {
            int r = edge_at(ei, (size_t)i);               // src
            int c = edge_at(ei, (size_t)N_EDGES + i);     // dst
            int pos = atomicAdd(&g_cursor[c], 1);
            csr[min(max(pos, 0), N_PAD_MAX - 1)] = r;
        } else if (i < N_RAW) {
            int n = i - N_EDGES;
            int pos = atomicAdd(&g_cursor[n], 1);
            csr[min(max(pos, 0), N_PAD_MAX - 1)] = n;     // self loop
        }
        return;
    }
    // ---- conv0: h'0 = dinv * (x @ W0 + b0) ----
    for (int i = threadIdx.x; i < IN_CH * HID; i += blockDim.x) Wsm[i] = W0[i];
    if (threadIdx.x < HID) bsm[threadIdx.x] = b0[threadIdx.x];
    __syncthreads();
    int node = (blockIdx.x - FILL_B) * 8 + (threadIdx.x >> 5);
    int lane = threadIdx.x & 31;
    if (node >= N_NODES) return;
    float xr[4];
#pragma unroll
    for (int q = 0; q < 4; q++) xr[q] = x[(size_t)node * IN_CH + q * 32 + lane];
    float y = bsm[lane];
#pragma unroll
    for (int q = 0; q < 4; q++)
#pragma unroll
        for (int c = 0; c < 32; c++) {
            float xv = __shfl_sync(0xffffffffu, xr[q], c);
            y = fmaf(xv, Wsm[(q * 32 + c) * HID + lane], y);
        }
    ((float*)g_h[0])[(size_t)node * 32 + lane] = y * g_dinv[node];
}

// ---------------- launches 6..36: SG layer (PDL-enabled) ----------------
// Pre-sync region: shared weight load only (host-written data).
// cudaGridDependencySynchronize() guards all reads of predecessor output.
__global__ void __launch_bounds__(256) k_sg_layer(int parity, const float* __restrict__ W,
                                                  const float* __restrict__ b) {
    __shared__ float Wsm[HID * HID];
    __shared__ float bsm[HID];
    for (int i = threadIdx.x; i < HID * HID; i += blockDim.x) Wsm[i] = W[i];
    if (threadIdx.x < HID) bsm[threadIdx.x] = b[threadIdx.x];
    // let the NEXT launch start dispatching/loading weights while we compute
    cudaTriggerProgrammaticLaunchCompletion();
    __syncthreads();
    // wait for predecessor grid (previous layer / fill+conv0) to fully complete
    cudaGridDependencySynchronize();

    int node = blockIdx.x * (blockDim.x >> 5) + (threadIdx.x >> 5);
    int lane = threadIdx.x & 31;
    if (node >= N_NODES) return;

    const float4* __restrict__ hin = g_h[parity];
    float* __restrict__ hout = (float*)g_h[parity ^ 1];

    int e4   = g_offs[node] >> 2;
    int end4 = g_offs[node + 1] >> 2;
    const int grp = lane >> 3, sub = lane & 7;

    float4 accA = make_float4(0.f, 0.f, 0.f, 0.f);
    float4 accB = make_float4(0.f, 0.f, 0.f, 0.f);
    for (; e4 + 2 <= end4; e4 += 2) {
        int4 sA = __ldg(&g_csr4[e4]);
        int4 sB = __ldg(&g_csr4[e4 + 1]);
        int srcA = (grp == 0) ? sA.x : (grp == 1) ? sA.y : (grp == 2) ? sA.z : sA.w;
        int srcB = (grp == 0) ? sB.x : (grp == 1) ? sB.y : (grp == 2) ? sB.z : sB.w;
        float4 vA = hin[(size_t)srcA * 8 + sub];
        float4 vB = hin[(size_t)srcB * 8 + sub];
        accA.x += vA.x; accA.y += vA.y; accA.z += vA.z; accA.w += vA.w;
        accB.x += vB.x; accB.y += vB.y; accB.z += vB.z; accB.w += vB.w;
    }
    if (e4 < end4) {
        int4 sA = __ldg(&g_csr4[e4]);
        int srcA = (grp == 0) ? sA.x : (grp == 1) ? sA.y : (grp == 2) ? sA.z : sA.w;
        float4 vA = hin[(size_t)srcA * 8 + sub];
        accA.x += vA.x; accA.y += vA.y; accA.z += vA.z; accA.w += vA.w;
    }
    accA.x += accB.x; accA.y += accB.y; accA.z += accB.z; accA.w += accB.w;

    // reduce across the 4 lane groups (channels live at fixed sub positions)
#pragma unroll
    for (int d = 8; d <= 16; d <<= 1) {
        accA.x += __shfl_xor_sync(0xffffffffu, accA.x, d);
        accA.y += __shfl_xor_sync(0xffffffffu, accA.y, d);
        accA.z += __shfl_xor_sync(0xffffffffu, accA.z, d);
        accA.w += __shfl_xor_sync(0xffffffffu, accA.w, d);
    }
    // remap: lane wants channel==lane (held at lane lane>>2, component lane&3)
    float a0 = __shfl_sync(0xffffffffu, accA.x, lane >> 2);
    float a1 = __shfl_sync(0xffffffffu, accA.y, lane >> 2);
    float a2 = __shfl_sync(0xffffffffu, accA.z, lane >> 2);
    float a3 = __shfl_sync(0xffffffffu, accA.w, lane >> 2);
    int m = lane & 3;
    float agg = (m == 0) ? a0 : (m == 1) ? a1 : (m == 2) ? a2 : a3;

    float dv = g_dinv[node];
    agg *= dv;

    float y = bsm[lane];
#pragma unroll
    for (int c = 0; c < 32; c++)
        y = fmaf(__shfl_sync(0xffffffffu, agg, c), Wsm[c * HID + lane], y);
    hout[(size_t)node * 32 + lane] = fmaxf(y, 0.f) * dv;   // pre-scale for next layer
}

// ---------------- final launch: out = h @ W32 + b32  (PDL-enabled) ----------------
__global__ void k_conv_out(int parity, const float* __restrict__ W32,
                           const float* __restrict__ b32, float* __restrict__ out) {
    __shared__ float Wsm[HID * OUT_CH];  // 8 KB
    __shared__ float bsm[OUT_CH];
    for (int i = threadIdx.x; i < HID * OUT_CH; i += blockDim.x) Wsm[i] = W32[i];
    if (threadIdx.x < OUT_CH) bsm[threadIdx.x] = b32[threadIdx.x];
    __syncthreads();
    cudaGridDependencySynchronize();
    int node = blockIdx.x * (blockDim.x >> 5) + (threadIdx.x >> 5);
    int lane = threadIdx.x & 31;
    if (node >= N_NODES) return;
    float hv = ((const float*)g_h[parity])[(size_t)node * 32 + lane]
               * sqrtf((float)g_deg[node]);   // undo the dinv pre-scale
    float y0 = bsm[lane], y1 = bsm[lane + 32];
#pragma unroll
    for (int c = 0; c < 32; c++) {
        float a = __shfl_sync(0xffffffffu, hv, c);
        y0 = fmaf(a, Wsm[c * OUT_CH + lane], y0);
        y1 = fmaf(a, Wsm[c * OUT_CH + lane + 32], y1);
    }
    out[(size_t)node * OUT_CH + lane]      = y0;
    out[(size_t)node * OUT_CH + lane + 32] = y1;
}

// ---------------- launch ----------------
extern "C" void kernel_launch(void* const* d_in, const int* in_sizes, int n_in,
                              void* d_out, int out_size) {
    const float* x = nullptr; const float* W0 = nullptr; const float* b0 = nullptr;
    const float* Ws = nullptr; const float* bs = nullptr;
    const float* W32 = nullptr; const float* b32 = nullptr;
    const void* ei = nullptr;
    for (int i = 0; i < n_in; i++) {
        switch (in_sizes[i]) {
            case 12800000: x   = (const float*)d_in[i]; break;
            case 4096:     W0  = (const float*)d_in[i]; break;
            case 32:       b0  = (const float*)d_in[i]; break;
            case 31744:    Ws  = (const float*)d_in[i]; break;
            case 992:      bs  = (const float*)d_in[i]; break;
            case 2048:     W32 = (const float*)d_in[i]; break;
            case 64:       b32 = (const float*)d_in[i]; break;
            case 6400000:  ei  = d_in[i]; break;
            default: break;
        }
    }
    if (!x || !W0 || !b0 || !Ws || !bs || !W32 || !b32 || !ei) return;

    float* out = (float*)d_out;
    const int T = 256;

    k_detect_init<<<(N_NODES + T - 1) / T, T>>>((const int*)ei);          // 1
    k_deg_accum<<<(N_EDGES + T - 1) / T, T>>>(ei);                        // 2
    k_scan_dinv<<<1, 1024>>>();                                           // 3
    k_prep<<<(N_PAD_MAX / 4 + T - 1) / T, T>>>();                         // 4
    k_fill_conv0<<<FILL_B + CONV_B, T>>>(ei, x, W0, b0);                  // 5

    // PDL config for the dependent chain
    cudaLaunchAttribute attrs[1];
    attrs[0].id = cudaLaunchAttributeProgrammaticStreamSerialization;
    attrs[0].val.programmaticStreamSerializationAllowed = 1;

    int parity = 0;
    for (int l = 0; l < N_SG; l++) {                                      // 6..36
        cudaLaunchConfig_t cfg = {};
        cfg.gridDim  = dim3(CONV_B, 1, 1);
        cfg.blockDim = dim3(T, 1, 1);
        cfg.dynamicSmemBytes = 0;
        cfg.stream = 0;
        cfg.attrs = attrs;
        cfg.numAttrs = 1;
        cudaLaunchKernelEx(&cfg, k_sg_layer, parity,
                           (const float*)(Ws + (size_t)l * HID * HID),
                           (const float*)(bs + (size_t)l * HID));
        parity ^= 1;
    }

    {
        cudaLaunchConfig_t cfg = {};
        cfg.gridDim  = dim3(CONV_B, 1, 1);
        cfg.blockDim = dim3(T, 1, 1);
        cfg.dynamicSmemBytes = 0;
        cfg.stream = 0;
        cfg.attrs = attrs;
        cfg.numAttrs = 1;
        cudaLaunchKernelEx(&cfg, k_conv_out, parity, W32, b32, out);      // 37
    }
}

// round 17
// speedup vs baseline: 2.0083x; 1.1329x over previous
#include <cuda_runtime.h>
#include <cuda_bf16.h>
#include <cstdint>

#define N_NODES 100000
#define N_EDGES 3200000
#define IN_CH   128
#define HID     32
#define OUT_CH  64
#define N_SG    31
#define N_RAW   (N_EDGES + N_NODES)          // edges + self loops (unpadded)
#define N_PAD_MAX (N_EDGES + 4 * N_NODES)    // padded CSR capacity (3.6M, mult of 4)

#define PG      888                          // persistent grid for k_pre: 148 SMs x 6
#define PWARPS  (PG * 8)
#define NPB     113                          // nodes per k_pre block (888*113 >= 100000)

// ---------------- device scratch (static globals; no allocation) ----------------
__device__ int    g_is64;
__device__ int    g_deg[N_NODES];
__device__ float  g_dinv[N_NODES];
__device__ int    g_offs[N_NODES + 1];
__device__ int    g_cursor[N_NODES];
__device__ int    g_part[PG];                        // per-block padded-degree sums
__device__ int4   g_csr4[N_PAD_MAX / 4];             // src indices, padded w/ sentinel N_NODES
__device__ float4 g_h[2][(size_t)(N_NODES + 1) * 8]; // ping-pong state (row N_NODES = zeros)
// grid barrier state (reset by k_init)
__device__ unsigned          g_count[2];
__device__ volatile unsigned g_gen;

// Safe edge accessor: idx in [0, 2*N_EDGES)
__device__ __forceinline__ int edge_at(const void* ei, size_t idx) {
    int v = g_is64 ? (int)((const long long*)ei)[idx]
                   : ((const int*)ei)[idx];
    return min(max(v, 0), N_NODES - 1);
}

// ---------------- launch 1: dtype detect + deg init + CSR sentinels + barrier reset ----------------
__global__ void k_init(const int* __restrict__ w) {
    int i = blockIdx.x * blockDim.x + threadIdx.x;
    if (i < N_NODES) g_deg[i] = 1;  // self loop
    if (i < N_PAD_MAX / 4) g_csr4[i] = make_int4(N_NODES, N_NODES, N_NODES, N_NODES);
    if (i < 64) {  // zero row N_NODES of both ping-pong buffers
        ((float*)g_h[i >> 5])[(size_t)N_NODES * 32 + (i & 31)] = 0.f;
    }
    if (i < 2) g_count[i] = 0u;
    if (i == 2) g_gen = 0u;
    if (blockIdx.x == 0) {
        __shared__ int any_nonzero;
        if (threadIdx.x == 0) any_nonzero = 0;
        __syncthreads();
        // sample odd int32 words over [0, 6.4M): all-zero <=> int64 payload
        size_t pos = (size_t)threadIdx.x * 24994 + 1;   // tid<256 -> max 6.37M
        if (w[pos] != 0) any_nonzero = 1;
        __syncthreads();
        if (threadIdx.x == 0) g_is64 = any_nonzero ? 0 : 1;
    }
}

// ---------------- launch 2: degree accumulation ----------------
__global__ void k_deg_accum(const void* __restrict__ ei) {
    int i = blockIdx.x * blockDim.x + threadIdx.x;
    if (i < N_EDGES) {
        int c = edge_at(ei, (size_t)N_EDGES + i);   // col = edge_index[1] (dst)
        atomicAdd(&g_deg[c], 1);
    }
}

// ---------------- launch 3: persistent — scan + CSR fill + conv0 ----------------
__device__ __forceinline__ void grid_barrier(int phase) {
    __syncthreads();
    if (threadIdx.x == 0) {
        __threadfence();
        unsigned t = atomicAdd(&g_count[phase], 1u);
        if (t == PG - 1u) {
            __threadfence();
            g_gen = (unsigned)(phase + 1);
        } else {
            while (g_gen < (unsigned)(phase + 1)) __nanosleep(64);
        }
        __threadfence();
    }
    __syncthreads();
}

__global__ void __launch_bounds__(256, 6) k_pre(const void* __restrict__ ei,
                                                const float* __restrict__ x,
                                                const float* __restrict__ W0,
                                                const float* __restrict__ b0) {
    __shared__ float Wsm[IN_CH * HID];   // 16 KB
    __shared__ float bsm[HID];
    __shared__ int   wsum[8];
    __shared__ int   sbase;
    const int tid  = threadIdx.x;
    const int wid  = tid >> 5;
    const int lane = tid & 31;
    const int b    = blockIdx.x;
    const int nbeg = b * NPB;
    const int nend = min(nbeg + NPB, N_NODES);

    // ---- phase 1: dinv + padded degree sum for this block's node range ----
    int s = 0;
    for (int i = nbeg + tid; i < nend; i += 256) {
        int d = g_deg[i];
        g_dinv[i] = rsqrtf((float)d);
        s += (d + 3) & ~3;
    }
#pragma unroll
    for (int d = 16; d >= 1; d >>= 1) s += __shfl_xor_sync(0xffffffffu, s, d);
    if (lane == 0) wsum[wid] = s;
    __syncthreads();
    if (tid == 0) {
        int t = 0;
#pragma unroll
        for (int i = 0; i < 8; i++) t += wsum[i];
        g_part[b] = t;
    }
    grid_barrier(0);

    // ---- phase 2: base = sum g_part[0..b); then warp 0 writes offs/cursor ----
    {
        int ps = 0;
        for (int i = tid; i < b; i += 256) ps += g_part[i];
#pragma unroll
        for (int d = 16; d >= 1; d >>= 1) ps += __shfl_xor_sync(0xffffffffu, ps, d);
        if (lane == 0) wsum[wid] = ps;
        __syncthreads();
        if (tid == 0) {
            int t = 0;
#pragma unroll
            for (int i = 0; i < 8; i++) t += wsum[i];
            sbase = t;
        }
        __syncthreads();
    }
    if (wid == 0) {
        int run = sbase;
        for (int s0 = nbeg; s0 < nend; s0 += 32) {
            int n = s0 + lane;
            int d = (n < nend) ? ((g_deg[n] + 3) & ~3) : 0;
            int inc = d;
#pragma unroll
            for (int off = 1; off < 32; off <<= 1) {
                int v = __shfl_up_sync(0xffffffffu, inc, off);
                if (lane >= off) inc += v;
            }
            if (n < nend) { g_offs[n] = run + inc - d; g_cursor[n] = run + inc - d; }
            run += __shfl_sync(0xffffffffu, inc, 31);
        }
        if (lane == 0 && b == (N_NODES - 1) / NPB) g_offs[N_NODES] = run;
    }
    grid_barrier(1);

    // ---- phase 3: CSR fill (grid-stride over edges + self loops) ----
    {
        int* csr = (int*)g_csr4;
        for (int i = b * 256 + tid; i < N_RAW; i += PG * 256) {
            if (i < N_EDGES) {
                int r = edge_at(ei, (size_t)i);               // src
                int c = edge_at(ei, (size_t)N_EDGES + i);     // dst
                int pos = atomicAdd(&g_cursor[c], 1);
                csr[min(max(pos, 0), N_PAD_MAX - 1)] = r;
            } else {
                int n = i - N_EDGES;
                int pos = atomicAdd(&g_cursor[n], 1);
                csr[min(max(pos, 0), N_PAD_MAX - 1)] = n;     // self loop
            }
        }
    }

    // ---- phase 4: conv0 h'0 = dinv * (x @ W0 + b0) (independent of fill) ----
    for (int i = tid; i < IN_CH * HID; i += 256) Wsm[i] = W0[i];
    if (tid < HID) bsm[tid] = b0[tid];
    __syncthreads();
    const int gwarp = b * 8 + wid;
    for (int node = gwarp; node < N_NODES; node += PWARPS) {
        float xr[4];
#pragma unroll
        for (int q = 0; q < 4; q++) xr[q] = x[(size_t)node * IN_CH + q * 32 + lane];
        float y = bsm[lane];
#pragma unroll
        for (int q = 0; q < 4; q++)
#pragma unroll
            for (int c = 0; c < 32; c++) {
                float xv = __shfl_sync(0xffffffffu, xr[q], c);
                y = fmaf(xv, Wsm[(q * 32 + c) * HID + lane], y);
            }
        ((float*)g_h[0])[(size_t)node * 32 + lane] = y * g_dinv[node];
    }
}

// ---------------- launches 4..34: SG layer (exact R8 best-known config) ----------------
#define CONV_B ((N_NODES + 7) / 8)           // 12500
__global__ void __launch_bounds__(256) k_sg_layer(int parity, const float* __restrict__ W,
                                                  const float* __restrict__ b) {
    __shared__ float Wsm[HID * HID];
    __shared__ float bsm[HID];
    for (int i = threadIdx.x; i < HID * HID; i += blockDim.x) Wsm[i] = W[i];
    if (threadIdx.x < HID) bsm[threadIdx.x] = b[threadIdx.x];
    __syncthreads();
    int node = blockIdx.x * (blockDim.x >> 5) + (threadIdx.x >> 5);
    int lane = threadIdx.x & 31;
    if (node >= N_NODES) return;

    const float4* __restrict__ hin = g_h[parity];
    float* __restrict__ hout = (float*)g_h[parity ^ 1];

    int e4   = g_offs[node] >> 2;
    int end4 = g_offs[node + 1] >> 2;
    const int grp = lane >> 3, sub = lane & 7;

    float4 accA = make_float4(0.f, 0.f, 0.f, 0.f);
    float4 accB = make_float4(0.f, 0.f, 0.f, 0.f);
    for (; e4 + 2 <= end4; e4 += 2) {
        int4 sA = __ldg(&g_csr4[e4]);
        int4 sB = __ldg(&g_csr4[e4 + 1]);
        int srcA = (grp == 0) ? sA.x : (grp == 1) ? sA.y : (grp == 2) ? sA.z : sA.w;
        int srcB = (grp == 0) ? sB.x : (grp == 1) ? sB.y : (grp == 2) ? sB.z : sB.w;
        float4 vA = hin[(size_t)srcA * 8 + sub];
        float4 vB = hin[(size_t)srcB * 8 + sub];
        accA.x += vA.x; accA.y += vA.y; accA.z += vA.z; accA.w += vA.w;
        accB.x += vB.x; accB.y += vB.y; accB.z += vB.z; accB.w += vB.w;
    }
    if (e4 < end4) {
        int4 sA = __ldg(&g_csr4[e4]);
        int srcA = (grp == 0) ? sA.x : (grp == 1) ? sA.y : (grp == 2) ? sA.z : sA.w;
        float4 vA = hin[(size_t)srcA * 8 + sub];
        accA.x += vA.x; accA.y += vA.y; accA.z += vA.z; accA.w += vA.w;
    }
    accA.x += accB.x; accA.y += accB.y; accA.z += accB.z; accA.w += accB.w;

    // reduce across the 4 lane groups (channels live at fixed sub positions)
#pragma unroll
    for (int d = 8; d <= 16; d <<= 1) {
        accA.x += __shfl_xor_sync(0xffffffffu, accA.x, d);
        accA.y += __shfl_xor_sync(0xffffffffu, accA.y, d);
        accA.z += __shfl_xor_sync(0xffffffffu, accA.z, d);
        accA.w += __shfl_xor_sync(0xffffffffu, accA.w, d);
    }
    // remap: lane wants channel==lane (held at lane lane>>2, component lane&3)
    float a0 = __shfl_sync(0xffffffffu, accA.x, lane >> 2);
    float a1 = __shfl_sync(0xffffffffu, accA.y, lane >> 2);
    float a2 = __shfl_sync(0xffffffffu, accA.z, lane >> 2);
    float a3 = __shfl_sync(0xffffffffu, accA.w, lane >> 2);
    int m = lane & 3;
    float agg = (m == 0) ? a0 : (m == 1) ? a1 : (m == 2) ? a2 : a3;

    float dv = g_dinv[node];
    agg *= dv;

    float y = bsm[lane];
#pragma unroll
    for (int c = 0; c < 32; c++)
        y = fmaf(__shfl_sync(0xffffffffu, agg, c), Wsm[c * HID + lane], y);
    hout[(size_t)node * 32 + lane] = fmaxf(y, 0.f) * dv;   // pre-scale for next layer
}

// ---------------- final launch: out = h @ W32 + b32 ----------------
__global__ void k_conv_out(int parity, const float* __restrict__ W32,
                           const float* __restrict__ b32, float* __restrict__ out) {
    __shared__ float Wsm[HID * OUT_CH];  // 8 KB
    __shared__ float bsm[OUT_CH];
    for (int i = threadIdx.x; i < HID * OUT_CH; i += blockDim.x) Wsm[i] = W32[i];
    if (threadIdx.x < OUT_CH) bsm[threadIdx.x] = b32[threadIdx.x];
    __syncthreads();
    int node = blockIdx.x * (blockDim.x >> 5) + (threadIdx.x >> 5);
    int lane = threadIdx.x & 31;
    if (node >= N_NODES) return;
    float hv = ((const float*)g_h[parity])[(size_t)node * 32 + lane]
               * sqrtf((float)g_deg[node]);   // undo the dinv pre-scale
    float y0 = bsm[lane], y1 = bsm[lane + 32];
#pragma unroll
    for (int c = 0; c < 32; c++) {
        float a = __shfl_sync(0xffffffffu, hv, c);
        y0 = fmaf(a, Wsm[c * OUT_CH + lane], y0);
        y1 = fmaf(a, Wsm[c * OUT_CH + lane + 32], y1);
    }
    out[(size_t)node * OUT_CH + lane]      = y0;
    out[(size_t)node * OUT_CH + lane + 32] = y1;
}

// ---------------- launch ----------------
extern "C" void kernel_launch(void* const* d_in, const int* in_sizes, int n_in,
                              void* d_out, int out_size) {
    const float* x = nullptr; const float* W0 = nullptr; const float* b0 = nullptr;
    const float* Ws = nullptr; const float* bs = nullptr;
    const float* W32 = nullptr; const float* b32 = nullptr;
    const void* ei = nullptr;
    for (int i = 0; i < n_in; i++) {
        switch (in_sizes[i]) {
            case 12800000: x   = (const float*)d_in[i]; break;
            case 4096:     W0  = (const float*)d_in[i]; break;
            case 32:       b0  = (const float*)d_in[i]; break;
            case 31744:    Ws  = (const float*)d_in[i]; break;
            case 992:      bs  = (const float*)d_in[i]; break;
            case 2048:     W32 = (const float*)d_in[i]; break;
            case 64:       b32 = (const float*)d_in[i]; break;
            case 6400000:  ei  = d_in[i]; break;
            default: break;
        }
    }
    if (!x || !W0 || !b0 || !Ws || !bs || !W32 || !b32 || !ei) return;

    float* out = (float*)d_out;
    const int T = 256;
    const int INIT_B = (N_PAD_MAX / 4 + T - 1) / T;   // covers all init ranges

    k_init<<<INIT_B, T>>>((const int*)ei);                                // 1
    k_deg_accum<<<(N_EDGES + T - 1) / T, T>>>(ei);                        // 2
    k_pre<<<PG, T>>>(ei, x, W0, b0);                                      // 3

    int parity = 0;
    for (int l = 0; l < N_SG; l++) {                                      // 4..34
        k_sg_layer<<<CONV_B, T>>>(parity, Ws + (size_t)l * HID * HID, bs + (size_t)l * HID);
        parity ^= 1;
    }

    k_conv_out<<<CONV_B, T>>>(parity, W32, b32, out);                     // 35
}